// round 13
// baseline (speedup 1.0000x reference)
#include <cuda_runtime.h>
#include <cstdint>

// ParallelVarPatchEmbed, persistent tf32 mma.sync kernel, 256 threads.
// R13: 64x64 warp tiles (halves LDS bytes per MAC vs 32x64). 4 warp-pairs,
// pair = (m-half, batch set of 4); each pair owns a private 2-stage cp.async
// A ring (64x32 tile, 8KB) + 64-thread named barrier. B resident in the
// paired-k pad-264 layout (single ld.shared.v2 per fragment, conflict-free).
// Grid: 8(rg) x 8(v) x 2(bg) = 128 persistent CTAs.

static constexpr int THREADS = 256;

static constexpr int BROW     = 264;                   // B row stride (pad 8)
static constexpr int BIAS_OFF = 0;
static constexpr int B_OFF    = 128;
static constexpr int A_OFF    = 128 + 128 * BROW;      // 33920
static constexpr int SMEM_FLOATS = A_OFF + 4 * 2 * 2048;   // 50304
static constexpr int SMEM_BYTES  = SMEM_FLOATS * 4;        // 201216

__device__ __forceinline__ uint32_t smem_u32(const void* p) {
    uint32_t a;
    asm("{ .reg .u64 t; cvta.to.shared.u64 t, %1; cvt.u32.u64 %0, t; }" : "=r"(a) : "l"(p));
    return a;
}
__device__ __forceinline__ void cpasync16(uint32_t dst, const float* src) {
    asm volatile("cp.async.cg.shared.global [%0], [%1], 16;" :: "r"(dst), "l"(src) : "memory");
}
__device__ __forceinline__ void cpcommit() {
    asm volatile("cp.async.commit_group;" ::: "memory");
}
template <int N> __device__ __forceinline__ void cpwait() {
    asm volatile("cp.async.wait_group %0;" :: "n"(N) : "memory");
}
__device__ __forceinline__ void barpair(int id) {
    asm volatile("bar.sync %0, 64;" :: "r"(id) : "memory");
}
__device__ __forceinline__ uint32_t f2tf32(float f) {
    uint32_t r;
    asm("cvt.rna.tf32.f32 %0, %1;" : "=r"(r) : "f"(f));
    return r;
}
__device__ __forceinline__ float lds_f(uint32_t addr) {
    float v;
    asm volatile("ld.shared.f32 %0, [%1];" : "=f"(v) : "r"(addr));
    return v;
}
__device__ __forceinline__ void lds_v2(uint32_t addr, uint32_t& v0, uint32_t& v1) {
    asm volatile("ld.shared.v2.b32 {%0, %1}, [%2];" : "=r"(v0), "=r"(v1) : "r"(addr));
}
__device__ __forceinline__ void mma8(float* c, const uint32_t* a, uint32_t b0, uint32_t b1) {
    asm volatile(
        "mma.sync.aligned.m16n8k8.row.col.f32.tf32.tf32.f32 "
        "{%0,%1,%2,%3}, {%4,%5,%6,%7}, {%8,%9}, {%0,%1,%2,%3};"
        : "+f"(c[0]), "+f"(c[1]), "+f"(c[2]), "+f"(c[3])
        : "r"(a[0]), "r"(a[1]), "r"(a[2]), "r"(a[3]), "r"(b0), "r"(b1));
}
// JAX demotes int64->int32 silently; detect layout from first 32 bytes.
__device__ __forceinline__ int get_var(const int* __restrict__ p32, int v) {
    bool is64 = ((p32[1] | p32[3] | p32[5] | p32[7]) == 0);
    return is64 ? p32[2 * v] : p32[v];
}

__global__ __launch_bounds__(THREADS, 1)
void pve_mma_kernel(const float* __restrict__ x,
                    const int* __restrict__ in_vars,
                    const float* __restrict__ w,
                    const float* __restrict__ bias,
                    float* __restrict__ out)
{
    extern __shared__ float smf[];
    const uint32_t sbase = smem_u32(smf);

    const int tid  = threadIdx.x;
    const int wid  = tid >> 5;
    const int lane = tid & 31;
    const int qrow = lane >> 2;     // 0..7
    const int qcol = lane & 3;      // 0..3
    const int pair = wid >> 1;      // 0..3
    const int wpos = wid & 1;       // n-half
    const int mh   = pair & 1;      // m-half (64 patches)
    const int bset = pair >> 1;     // batch set of 4 within bg
    const int ptid = wpos * 32 + lane;   // 0..63 within pair
    const int n0   = wpos * 64;

    const int rg = blockIdx.x, v = blockIdx.y, bg = blockIdx.z;
    const int var = get_var(in_vars, v);

    const float* wbase = w + (size_t)var * (128 * 256);

    if (tid < 128) smf[BIAS_OFF + tid] = bias[var * 128 + tid];

    // ---- B prologue (all threads): W[var] -> tf32 -> flat [128][264] paired-k ----
    #pragma unroll
    for (int i = 0; i < 32; i++) {
        int idx = tid + 256 * i;            // 0..8191 float4s
        int e   = idx >> 6;                 // 0..127
        int k4  = idx & 63;
        int k   = k4 * 4;
        float4 vsrc = *reinterpret_cast<const float4*>(wbase + (size_t)e * 256 + k4 * 4);
        float* row = smf + B_OFF + e * BROW;
        int base = (k >> 3) * 8 + ((k >> 2) & 1);
        row[base + 0] = __uint_as_float(f2tf32(vsrc.x));
        row[base + 2] = __uint_as_float(f2tf32(vsrc.y));
        row[base + 4] = __uint_as_float(f2tf32(vsrc.z));
        row[base + 6] = __uint_as_float(f2tf32(vsrc.w));
    }
    __syncthreads();   // last CTA-wide barrier; pairs run free after this

    // ---- per-thread invariant copy mapping: 64x32 A tile (2048 fl) = 512 f4s ----
    // idx = ptid + 64*i (i 0..7): rl = idx>>7 (0..3): prl = rl>>1, dp = rl&1;
    // c4 = idx&127: pc = c4>>2, q0 = (c4&3)*4. ml = prl*32+pc, kl = dp*16+q0.
    uint32_t dst_inv[8];
    int      src_inv[8];
    #pragma unroll
    for (int i = 0; i < 8; i++) {
        int idx = ptid + 64 * i;
        int rl  = idx >> 7, c4 = idx & 127;
        int prl = rl >> 1, dp = rl & 1;
        int ml  = prl * 32 + (c4 >> 2);
        int kl  = dp * 16 + (c4 & 3) * 4;
        dst_inv[i] = (uint32_t)(ml * 32 + (kl ^ ((ml & 7) * 4)));
        src_inv[i] = (prl * 16 + dp) * 512 + c4 * 4;
    }

    const uint32_t apair = (uint32_t)(A_OFF + pair * 4096);
    const float* xpr[4];
    #pragma unroll
    for (int bi = 0; bi < 4; bi++) {
        int b = bg * 8 + bset * 4 + bi;
        xpr[bi] = x + (size_t)(b * 8 + v) * (512 * 512)
                    + (size_t)(rg * 64 + mh * 32) * 512;   // mh*2 patch rows = 32 image rows
    }

    auto issueA = [&](int t) {
        const float* src = xpr[t >> 3] + (t & 7) * 1024;   // ch*2 image rows
        const uint32_t abase = sbase + (apair + (uint32_t)((t & 1) * 2048)) * 4;
        #pragma unroll
        for (int i = 0; i < 8; i++)
            cpasync16(abase + dst_inv[i] * 4, src + src_inv[i]);
        cpcommit();
    };

    // loop-invariant fragment offsets
    uint32_t koff[4][2];
    #pragma unroll
    for (int ks = 0; ks < 4; ks++) {
        koff[ks][0] = (uint32_t)(((ks * 8 + qcol)     ^ (qrow * 4)) * 4);
        koff[ks][1] = (uint32_t)(((ks * 8 + qcol + 4) ^ (qrow * 4)) * 4);
    }
    const uint32_t arow0  = (uint32_t)qrow * 128;
    const uint32_t bfrag0 = (uint32_t)(B_OFF + (n0 + qrow) * BROW + qcol * 2) * 4;

    float acc[4][8][4];
    #pragma unroll
    for (int mf = 0; mf < 4; mf++)
        #pragma unroll
        for (int nf = 0; nf < 8; nf++)
            #pragma unroll
            for (int j = 0; j < 4; j++) acc[mf][nf][j] = 0.0f;

    issueA(0);

    #pragma unroll 1
    for (int t = 0; t < 32; t++) {
        cpwait<0>();
        barpair(pair + 1);           // both warps: chunk t visible, old slot consumed
        if (t + 1 < 32) issueA(t + 1);

        const uint32_t aR0 = sbase + (apair + (uint32_t)((t & 1) * 2048)) * 4 + arow0;
        const uint32_t bR0 = sbase + bfrag0 + (uint32_t)(t & 7) * 128;

        #pragma unroll
        for (int ks = 0; ks < 4; ks++) {
            const uint32_t k0 = koff[ks][0], k1 = koff[ks][1];
            uint32_t a[4][4];
            #pragma unroll
            for (int mf = 0; mf < 4; mf++) {
                const uint32_t r0 = aR0 + (uint32_t)(mf * 16) * 128;
                a[mf][0] = f2tf32(lds_f(r0 + k0));
                a[mf][1] = f2tf32(lds_f(r0 + 8 * 128 + k0));
                a[mf][2] = f2tf32(lds_f(r0 + k1));
                a[mf][3] = f2tf32(lds_f(r0 + 8 * 128 + k1));
            }
            const uint32_t bks = bR0 + (uint32_t)(ks * 32);
            #pragma unroll
            for (int nf = 0; nf < 8; nf++) {
                uint32_t b0, b1;
                lds_v2(bks + (uint32_t)(nf * 8) * (BROW * 4), b0, b1);
                #pragma unroll
                for (int mf = 0; mf < 4; mf++)
                    mma8(acc[mf][nf], a[mf], b0, b1);
            }
        }

        if ((t & 7) == 7) {
            // ---- epilogue for batch b = bg*8 + bset*4 + (t>>3) ----
            const int b = bg * 8 + bset * 4 + (t >> 3);
            float* obase = out + (((size_t)(b * 8 + v) * 1024) + (size_t)rg * 128) * 128;
            const float* bs = smf + BIAS_OFF;
            #pragma unroll
            for (int mf = 0; mf < 4; mf++) {
                const int r = mh * 64 + mf * 16 + qrow;
                #pragma unroll
                for (int nf = 0; nf < 8; nf++) {
                    const int e0 = n0 + nf * 8 + qcol * 2;
                    float2 lo, hi;
                    lo.x = acc[mf][nf][0] + bs[e0];
                    lo.y = acc[mf][nf][1] + bs[e0 + 1];
                    hi.x = acc[mf][nf][2] + bs[e0];
                    hi.y = acc[mf][nf][3] + bs[e0 + 1];
                    *reinterpret_cast<float2*>(obase + (size_t)r * 128 + e0)       = lo;
                    *reinterpret_cast<float2*>(obase + (size_t)(r + 8) * 128 + e0) = hi;
                    acc[mf][nf][0] = 0.0f; acc[mf][nf][1] = 0.0f;
                    acc[mf][nf][2] = 0.0f; acc[mf][nf][3] = 0.0f;
                }
            }
        }
    }
}

extern "C" void kernel_launch(void* const* d_in, const int* in_sizes, int n_in,
                              void* d_out, int out_size)
{
    const float* x       = (const float*)d_in[0];
    const int*   in_vars = (const int*)d_in[1];
    const float* w       = (const float*)d_in[2];
    const float* bias    = (const float*)d_in[3];
    float*       out     = (float*)d_out;

    cudaFuncSetAttribute(pve_mma_kernel,
                         cudaFuncAttributeMaxDynamicSharedMemorySize, SMEM_BYTES);

    dim3 grid(8, 8, 2);    // (row group, V, batch group) -> 128 persistent CTAs
    pve_mma_kernel<<<grid, THREADS, SMEM_BYTES>>>(x, in_vars, w, bias, out);
}

// round 14
// speedup vs baseline: 1.0390x; 1.0390x over previous
#include <cuda_runtime.h>
#include <cstdint>

// ParallelVarPatchEmbed, persistent tf32 mma.sync kernel, 512 threads.
// R14 = R12 (warp-pair decoupled, pair-private cp.async rings, resident
// paired-k B) + A fragments fed as RAW fp32 bits (HW tf32 truncation, no cvt):
// removes 32 cvt.rna per warp-chunk and a 4-cyc stage from every LDS->MMA chain.
// B keeps RNA rounding in the (amortized) prologue.

static constexpr int THREADS = 512;

static constexpr int BROW     = 264;                   // B row stride (pad 8)
static constexpr int BIAS_OFF = 0;
static constexpr int B_OFF    = 128;
static constexpr int A_OFF    = 128 + 128 * BROW;      // 33920
static constexpr int SMEM_FLOATS = A_OFF + 8 * 2 * 1024;   // 50304
static constexpr int SMEM_BYTES  = SMEM_FLOATS * 4;        // 201216

__device__ __forceinline__ uint32_t smem_u32(const void* p) {
    uint32_t a;
    asm("{ .reg .u64 t; cvta.to.shared.u64 t, %1; cvt.u32.u64 %0, t; }" : "=r"(a) : "l"(p));
    return a;
}
__device__ __forceinline__ void cpasync16(uint32_t dst, const float* src) {
    asm volatile("cp.async.cg.shared.global [%0], [%1], 16;" :: "r"(dst), "l"(src) : "memory");
}
__device__ __forceinline__ void cpcommit() {
    asm volatile("cp.async.commit_group;" ::: "memory");
}
template <int N> __device__ __forceinline__ void cpwait() {
    asm volatile("cp.async.wait_group %0;" :: "n"(N) : "memory");
}
__device__ __forceinline__ void barpair(int id) {
    asm volatile("bar.sync %0, 64;" :: "r"(id) : "memory");
}
__device__ __forceinline__ uint32_t f2tf32(float f) {
    uint32_t r;
    asm("cvt.rna.tf32.f32 %0, %1;" : "=r"(r) : "f"(f));
    return r;
}
__device__ __forceinline__ uint32_t lds_u(uint32_t addr) {
    uint32_t v;
    asm volatile("ld.shared.b32 %0, [%1];" : "=r"(v) : "r"(addr));
    return v;
}
__device__ __forceinline__ void lds_v2(uint32_t addr, uint32_t& v0, uint32_t& v1) {
    asm volatile("ld.shared.v2.b32 {%0, %1}, [%2];" : "=r"(v0), "=r"(v1) : "r"(addr));
}
__device__ __forceinline__ void mma8(float* c, const uint32_t* a, uint32_t b0, uint32_t b1) {
    asm volatile(
        "mma.sync.aligned.m16n8k8.row.col.f32.tf32.tf32.f32 "
        "{%0,%1,%2,%3}, {%4,%5,%6,%7}, {%8,%9}, {%0,%1,%2,%3};"
        : "+f"(c[0]), "+f"(c[1]), "+f"(c[2]), "+f"(c[3])
        : "r"(a[0]), "r"(a[1]), "r"(a[2]), "r"(a[3]), "r"(b0), "r"(b1));
}
// JAX demotes int64->int32 silently; detect layout from first 32 bytes.
__device__ __forceinline__ int get_var(const int* __restrict__ p32, int v) {
    bool is64 = ((p32[1] | p32[3] | p32[5] | p32[7]) == 0);
    return is64 ? p32[2 * v] : p32[v];
}

__global__ __launch_bounds__(THREADS, 1)
void pve_mma_kernel(const float* __restrict__ x,
                    const int* __restrict__ in_vars,
                    const float* __restrict__ w,
                    const float* __restrict__ bias,
                    float* __restrict__ out)
{
    extern __shared__ float smf[];
    const uint32_t sbase = smem_u32(smf);

    const int tid  = threadIdx.x;
    const int wid  = tid >> 5;
    const int lane = tid & 31;
    const int qrow = lane >> 2;     // 0..7
    const int qcol = lane & 3;      // 0..3
    const int pair = wid >> 1;      // 0..7
    const int wpos = wid & 1;       // n-half
    const int pr   = pair & 3;      // m-quarter (patch row group)
    const int bset = pair >> 2;     // batch half within bg
    const int ptid = wpos * 32 + lane;   // 0..63 within pair
    const int n0   = wpos * 64;

    const int rg = blockIdx.x, v = blockIdx.y, bg = blockIdx.z;
    const int var = get_var(in_vars, v);

    const float* wbase = w + (size_t)var * (128 * 256);

    if (tid < 128) smf[BIAS_OFF + tid] = bias[var * 128 + tid];

    // ---- B prologue (all threads): W[var] -> tf32 (RNA) -> flat [128][264] paired-k ----
    #pragma unroll
    for (int i = 0; i < 16; i++) {
        int idx = tid + 512 * i;            // 0..8191 float4s
        int e   = idx >> 6;                 // 0..127
        int k4  = idx & 63;
        int k   = k4 * 4;
        float4 vsrc = *reinterpret_cast<const float4*>(wbase + (size_t)e * 256 + k4 * 4);
        float* row = smf + B_OFF + e * BROW;
        int base = (k >> 3) * 8 + ((k >> 2) & 1);
        row[base + 0] = __uint_as_float(f2tf32(vsrc.x));
        row[base + 2] = __uint_as_float(f2tf32(vsrc.y));
        row[base + 4] = __uint_as_float(f2tf32(vsrc.z));
        row[base + 6] = __uint_as_float(f2tf32(vsrc.w));
    }
    __syncthreads();   // last CTA-wide barrier; pairs run free after this

    // ---- per-thread invariant copy mapping (4 x 16B per chunk) ----
    uint32_t dst_inv[4];
    int      src_inv[4];
    #pragma unroll
    for (int i = 0; i < 4; i++) {
        int idx = ptid + 64 * i;
        int dp  = idx >> 7, c4 = idx & 127;
        int mp  = c4 >> 2;
        int kl  = dp * 16 + (c4 & 3) * 4;
        dst_inv[i] = (uint32_t)(mp * 32 + (kl ^ ((mp & 7) * 4)));
        src_inv[i] = dp * 512 + c4 * 4;
    }

    const uint32_t apair = (uint32_t)(A_OFF + pair * 2048);
    const float* xpr[4];
    #pragma unroll
    for (int bi = 0; bi < 4; bi++) {
        int b = bg * 8 + bset * 4 + bi;
        xpr[bi] = x + (size_t)(b * 8 + v) * (512 * 512)
                    + (size_t)(rg * 64 + pr * 16) * 512;
    }

    auto issueA = [&](int t) {
        const float* src = xpr[t >> 3] + (t & 7) * 1024;   // ch*2 image rows
        const uint32_t abase = sbase + (apair + (uint32_t)((t & 1) * 1024)) * 4;
        #pragma unroll
        for (int i = 0; i < 4; i++)
            cpasync16(abase + dst_inv[i] * 4, src + src_inv[i]);
        cpcommit();
    };

    // loop-invariant fragment offsets
    uint32_t koff[4][2];
    #pragma unroll
    for (int ks = 0; ks < 4; ks++) {
        koff[ks][0] = (uint32_t)(((ks * 8 + qcol)     ^ (qrow * 4)) * 4);
        koff[ks][1] = (uint32_t)(((ks * 8 + qcol + 4) ^ (qrow * 4)) * 4);
    }
    const uint32_t arow0  = (uint32_t)qrow * 128;
    const uint32_t bfrag0 = (uint32_t)(B_OFF + (n0 + qrow) * BROW + qcol * 2) * 4;

    float acc[2][8][4];
    #pragma unroll
    for (int mf = 0; mf < 2; mf++)
        #pragma unroll
        for (int nf = 0; nf < 8; nf++)
            #pragma unroll
            for (int j = 0; j < 4; j++) acc[mf][nf][j] = 0.0f;

    issueA(0);

    #pragma unroll 1
    for (int t = 0; t < 32; t++) {
        cpwait<0>();
        barpair(pair + 1);           // both warps: chunk t visible, old slot consumed
        if (t + 1 < 32) issueA(t + 1);

        const uint32_t aR0 = sbase + (apair + (uint32_t)((t & 1) * 1024)) * 4 + arow0;
        const uint32_t bR0 = sbase + bfrag0 + (uint32_t)(t & 7) * 128;

        #pragma unroll
        for (int ks = 0; ks < 4; ks++) {
            const uint32_t k0 = koff[ks][0], k1 = koff[ks][1];
            uint32_t a[2][4];
            #pragma unroll
            for (int mf = 0; mf < 2; mf++) {
                const uint32_t r0 = aR0 + (uint32_t)(mf * 16) * 128;
                // raw fp32 bits as tf32 operands: HW ignores low 13 bits (RZ)
                a[mf][0] = lds_u(r0 + k0);
                a[mf][1] = lds_u(r0 + 8 * 128 + k0);
                a[mf][2] = lds_u(r0 + k1);
                a[mf][3] = lds_u(r0 + 8 * 128 + k1);
            }
            const uint32_t bks = bR0 + (uint32_t)(ks * 32);
            #pragma unroll
            for (int nf = 0; nf < 8; nf++) {
                uint32_t b0, b1;
                lds_v2(bks + (uint32_t)(nf * 8) * (BROW * 4), b0, b1);
                mma8(acc[0][nf], a[0], b0, b1);
                mma8(acc[1][nf], a[1], b0, b1);
            }
        }

        if ((t & 7) == 7) {
            // ---- epilogue for batch b = bg*8 + bset*4 + (t>>3) ----
            const int b = bg * 8 + bset * 4 + (t >> 3);
            float* obase = out + (((size_t)(b * 8 + v) * 1024) + (size_t)rg * 128) * 128;
            const float* bs = smf + BIAS_OFF;
            #pragma unroll
            for (int mf = 0; mf < 2; mf++) {
                const int r = pr * 32 + mf * 16 + qrow;
                #pragma unroll
                for (int nf = 0; nf < 8; nf++) {
                    const int e0 = n0 + nf * 8 + qcol * 2;
                    float2 lo, hi;
                    lo.x = acc[mf][nf][0] + bs[e0];
                    lo.y = acc[mf][nf][1] + bs[e0 + 1];
                    hi.x = acc[mf][nf][2] + bs[e0];
                    hi.y = acc[mf][nf][3] + bs[e0 + 1];
                    *reinterpret_cast<float2*>(obase + (size_t)r * 128 + e0)       = lo;
                    *reinterpret_cast<float2*>(obase + (size_t)(r + 8) * 128 + e0) = hi;
                    acc[mf][nf][0] = 0.0f; acc[mf][nf][1] = 0.0f;
                    acc[mf][nf][2] = 0.0f; acc[mf][nf][3] = 0.0f;
                }
            }
        }
    }
}

extern "C" void kernel_launch(void* const* d_in, const int* in_sizes, int n_in,
                              void* d_out, int out_size)
{
    const float* x       = (const float*)d_in[0];
    const int*   in_vars = (const int*)d_in[1];
    const float* w       = (const float*)d_in[2];
    const float* bias    = (const float*)d_in[3];
    float*       out     = (float*)d_out;

    cudaFuncSetAttribute(pve_mma_kernel,
                         cudaFuncAttributeMaxDynamicSharedMemorySize, SMEM_BYTES);

    dim3 grid(8, 8, 2);    // (row group, V, batch group) -> 128 persistent CTAs
    pve_mma_kernel<<<grid, THREADS, SMEM_BYTES>>>(x, in_vars, w, bias, out);
}

// round 15
// speedup vs baseline: 1.3065x; 1.2574x over previous
#include <cuda_runtime.h>
#include <cstdint>

// ParallelVarPatchEmbed, persistent FP16 mma.sync(m16n8k16) kernel, 512 threads.
// R15 = R14 structure (8 decoupled warp-pairs, pair-private cp.async A rings,
// resident B) with the math moved to fp16 HMMA (2x tf32 rate):
//  - B: W[var] -> cvt.rn fp16 -> resident SMEM, f16x2 words, row stride 136,
//    b0/b1 adjacent -> one conflict-free LDS.64 per B fragment.
//  - A: fp32 in SMEM (rotation layout word = m*32 + ((k+8*(m&7))&31)),
//    fragments via LDS.64 pair + cvt.rn.f16x2.f32 (conflict-free).
//  - Accumulate fp32; bias epilogue unchanged.

static constexpr int THREADS = 512;

static constexpr int BIAS_OFF = 0;
static constexpr int B_OFF    = 128;                      // B: 128 rows x 136 u32
static constexpr int A_OFF    = 128 + 128 * 136;          // 17536
static constexpr int SMEM_FLOATS = A_OFF + 8 * 2 * 1024;  // 33920
static constexpr int SMEM_BYTES  = SMEM_FLOATS * 4;       // 135680

__device__ __forceinline__ uint32_t smem_u32(const void* p) {
    uint32_t a;
    asm("{ .reg .u64 t; cvta.to.shared.u64 t, %1; cvt.u32.u64 %0, t; }" : "=r"(a) : "l"(p));
    return a;
}
__device__ __forceinline__ void cpasync16(uint32_t dst, const float* src) {
    asm volatile("cp.async.cg.shared.global [%0], [%1], 16;" :: "r"(dst), "l"(src) : "memory");
}
__device__ __forceinline__ void cpcommit() {
    asm volatile("cp.async.commit_group;" ::: "memory");
}
template <int N> __device__ __forceinline__ void cpwait() {
    asm volatile("cp.async.wait_group %0;" :: "n"(N) : "memory");
}
__device__ __forceinline__ void barpair(int id) {
    asm volatile("bar.sync %0, 64;" :: "r"(id) : "memory");
}
// pack two f32 -> f16x2 (lo = first k, hi = second k)
__device__ __forceinline__ uint32_t pack_h2(float lo, float hi) {
    uint32_t r;
    asm("cvt.rn.f16x2.f32 %0, %1, %2;" : "=r"(r) : "f"(hi), "f"(lo));
    return r;
}
__device__ __forceinline__ void lds_v2f(uint32_t addr, float& f0, float& f1) {
    asm volatile("ld.shared.v2.f32 {%0, %1}, [%2];" : "=f"(f0), "=f"(f1) : "r"(addr));
}
__device__ __forceinline__ void lds_v2u(uint32_t addr, uint32_t& v0, uint32_t& v1) {
    asm volatile("ld.shared.v2.b32 {%0, %1}, [%2];" : "=r"(v0), "=r"(v1) : "r"(addr));
}
__device__ __forceinline__ void mma16(float* c, const uint32_t* a, uint32_t b0, uint32_t b1) {
    asm volatile(
        "mma.sync.aligned.m16n8k16.row.col.f32.f16.f16.f32 "
        "{%0,%1,%2,%3}, {%4,%5,%6,%7}, {%8,%9}, {%0,%1,%2,%3};"
        : "+f"(c[0]), "+f"(c[1]), "+f"(c[2]), "+f"(c[3])
        : "r"(a[0]), "r"(a[1]), "r"(a[2]), "r"(a[3]), "r"(b0), "r"(b1));
}
// JAX demotes int64->int32 silently; detect layout from first 32 bytes.
__device__ __forceinline__ int get_var(const int* __restrict__ p32, int v) {
    bool is64 = ((p32[1] | p32[3] | p32[5] | p32[7]) == 0);
    return is64 ? p32[2 * v] : p32[v];
}

__global__ __launch_bounds__(THREADS, 1)
void pve_mma_kernel(const float* __restrict__ x,
                    const int* __restrict__ in_vars,
                    const float* __restrict__ w,
                    const float* __restrict__ bias,
                    float* __restrict__ out)
{
    extern __shared__ float smf[];
    const uint32_t sbase = smem_u32(smf);

    const int tid  = threadIdx.x;
    const int wid  = tid >> 5;
    const int lane = tid & 31;
    const int qrow = lane >> 2;     // 0..7
    const int qcol = lane & 3;      // 0..3
    const int pair = wid >> 1;      // 0..7
    const int wpos = wid & 1;       // n-half
    const int pr   = pair & 3;      // m-quarter (patch row group)
    const int bset = pair >> 2;     // batch half within bg
    const int ptid = wpos * 32 + lane;
    const int n0   = wpos * 64;

    const int rg = blockIdx.x, v = blockIdx.y, bg = blockIdx.z;
    const int var = get_var(in_vars, v);

    const float* wbase = w + (size_t)var * (128 * 256);

    if (tid < 128) smf[BIAS_OFF + tid] = bias[var * 128 + tid];

    // ---- B prologue: W[var] -> fp16 -> resident [128 rows][136 u32] ----
    // pair p holds fp16 (2p, 2p+1); stored at local = (p&3)*2 + ((p>>2)&1)
    // within group g = p>>3 -> b0 (p = g*8+qcol) and b1 (p = g*8+qcol+4) adjacent.
    uint32_t* bres = reinterpret_cast<uint32_t*>(smf + B_OFF);
    #pragma unroll
    for (int i = 0; i < 16; i++) {
        int idx = tid + 512 * i;            // 0..8191 float4s
        int e   = idx >> 6;                 // 0..127
        int k4  = idx & 63;
        float4 vsrc = *reinterpret_cast<const float4*>(wbase + (size_t)e * 256 + k4 * 4);
        uint32_t p0 = pack_h2(vsrc.x, vsrc.y);   // pair 2*k4
        uint32_t p1 = pack_h2(vsrc.z, vsrc.w);   // pair 2*k4+1
        int pa = 2 * k4, pb = 2 * k4 + 1;
        uint32_t* row = bres + e * 136;
        row[(pa >> 3) * 8 + (pa & 3) * 2 + ((pa >> 2) & 1)] = p0;
        row[(pb >> 3) * 8 + (pb & 3) * 2 + ((pb >> 2) & 1)] = p1;
    }
    __syncthreads();   // last CTA-wide barrier; pairs run free after this

    // ---- per-thread invariant A copy mapping (rotation layout) ----
    uint32_t dst_inv[4];
    int      src_inv[4];
    #pragma unroll
    for (int i = 0; i < 4; i++) {
        int idx = ptid + 64 * i;
        int dp  = idx >> 7, c4 = idx & 127;
        int mp  = c4 >> 2;
        int kl  = dp * 16 + (c4 & 3) * 4;
        dst_inv[i] = (uint32_t)(mp * 32 + ((kl + 8 * (mp & 7)) & 31));
        src_inv[i] = dp * 512 + c4 * 4;
    }

    const uint32_t apair = (uint32_t)(A_OFF + pair * 2048);
    const float* xpr[4];
    #pragma unroll
    for (int bi = 0; bi < 4; bi++) {
        int b = bg * 8 + bset * 4 + bi;
        xpr[bi] = x + (size_t)(b * 8 + v) * (512 * 512)
                    + (size_t)(rg * 64 + pr * 16) * 512;
    }

    auto issueA = [&](int t) {
        const float* src = xpr[t >> 3] + (t & 7) * 1024;
        const uint32_t abase = sbase + (apair + (uint32_t)((t & 1) * 1024)) * 4;
        #pragma unroll
        for (int i = 0; i < 4; i++)
            cpasync16(abase + dst_inv[i] * 4, src + src_inv[i]);
        cpcommit();
    };

    // loop-invariant fragment offsets
    // A: k16 step s (0/1): k pairs at k = s*16 + qcol*2 (+8), rotated by 8*qrow
    uint32_t akoff[2][2];
    #pragma unroll
    for (int s = 0; s < 2; s++) {
        akoff[s][0] = (uint32_t)(((s * 16 + qcol * 2     + 8 * qrow) & 31) * 4);
        akoff[s][1] = (uint32_t)(((s * 16 + qcol * 2 + 8 + 8 * qrow) & 31) * 4);
    }
    const uint32_t arow0 = (uint32_t)qrow * 128;      // bytes within A tile
    // B: u32 offset = row*136 + g*8 + qcol*2 ; row = n0 + nf*8 + qrow
    const uint32_t bfrag0 = (uint32_t)(B_OFF + (n0 + qrow) * 136 + qcol * 2) * 4;

    float acc[2][8][4];
    #pragma unroll
    for (int mf = 0; mf < 2; mf++)
        #pragma unroll
        for (int nf = 0; nf < 8; nf++)
            #pragma unroll
            for (int j = 0; j < 4; j++) acc[mf][nf][j] = 0.0f;

    issueA(0);

    #pragma unroll 1
    for (int t = 0; t < 32; t++) {
        cpwait<0>();
        barpair(pair + 1);
        if (t + 1 < 32) issueA(t + 1);

        const uint32_t aR0 = sbase + (apair + (uint32_t)((t & 1) * 1024)) * 4 + arow0;
        const uint32_t bR0 = sbase + bfrag0 + (uint32_t)((t & 7) * 2) * 32;  // g = 2*(t&7)+s

        #pragma unroll
        for (int s = 0; s < 2; s++) {           // two k16 steps per chunk
            const uint32_t k0 = akoff[s][0], k1 = akoff[s][1];
            uint32_t a[2][4];
            #pragma unroll
            for (int mf = 0; mf < 2; mf++) {
                const uint32_t r0 = aR0 + (uint32_t)(mf * 16) * 128;
                float f0, f1;
                lds_v2f(r0 + k0,           f0, f1); a[mf][0] = pack_h2(f0, f1);
                lds_v2f(r0 + 8 * 128 + k0, f0, f1); a[mf][1] = pack_h2(f0, f1);
                lds_v2f(r0 + k1,           f0, f1); a[mf][2] = pack_h2(f0, f1);
                lds_v2f(r0 + 8 * 128 + k1, f0, f1); a[mf][3] = pack_h2(f0, f1);
            }
            const uint32_t bks = bR0 + (uint32_t)(s * 8) * 4;
            #pragma unroll
            for (int nf = 0; nf < 8; nf++) {
                uint32_t b0, b1;
                lds_v2u(bks + (uint32_t)(nf * 8) * (136 * 4), b0, b1);
                mma16(acc[0][nf], a[0], b0, b1);
                mma16(acc[1][nf], a[1], b0, b1);
            }
        }

        if ((t & 7) == 7) {
            const int b = bg * 8 + bset * 4 + (t >> 3);
            float* obase = out + (((size_t)(b * 8 + v) * 1024) + (size_t)rg * 128) * 128;
            const float* bs = smf + BIAS_OFF;
            #pragma unroll
            for (int mf = 0; mf < 2; mf++) {
                const int r = pr * 32 + mf * 16 + qrow;
                #pragma unroll
                for (int nf = 0; nf < 8; nf++) {
                    const int e0 = n0 + nf * 8 + qcol * 2;
                    float2 lo, hi;
                    lo.x = acc[mf][nf][0] + bs[e0];
                    lo.y = acc[mf][nf][1] + bs[e0 + 1];
                    hi.x = acc[mf][nf][2] + bs[e0];
                    hi.y = acc[mf][nf][3] + bs[e0 + 1];
                    *reinterpret_cast<float2*>(obase + (size_t)r * 128 + e0)       = lo;
                    *reinterpret_cast<float2*>(obase + (size_t)(r + 8) * 128 + e0) = hi;
                    acc[mf][nf][0] = 0.0f; acc[mf][nf][1] = 0.0f;
                    acc[mf][nf][2] = 0.0f; acc[mf][nf][3] = 0.0f;
                }
            }
        }
    }
}

extern "C" void kernel_launch(void* const* d_in, const int* in_sizes, int n_in,
                              void* d_out, int out_size)
{
    const float* x       = (const float*)d_in[0];
    const int*   in_vars = (const int*)d_in[1];
    const float* w       = (const float*)d_in[2];
    const float* bias    = (const float*)d_in[3];
    float*       out     = (float*)d_out;

    cudaFuncSetAttribute(pve_mma_kernel,
                         cudaFuncAttributeMaxDynamicSharedMemorySize, SMEM_BYTES);

    dim3 grid(8, 8, 2);    // (row group, V, batch group) -> 128 persistent CTAs
    pve_mma_kernel<<<grid, THREADS, SMEM_BYTES>>>(x, in_vars, w, bias, out);
}

// round 17
// speedup vs baseline: 1.3661x; 1.0457x over previous
#include <cuda_runtime.h>
#include <cstdint>

// ParallelVarPatchEmbed, persistent FP16 mma.sync(m16n8k16) kernel, 512 threads.
// R16 = R15 + 4-stage pair-private A rings (prefetch distance 3, cp.async.wait_group 2)
// to cover DRAM latency that the 2-stage ring exposed every iteration.

static constexpr int THREADS = 512;

static constexpr int BIAS_OFF = 0;
static constexpr int B_OFF    = 128;                      // B: 128 rows x 136 u32
static constexpr int A_OFF    = 128 + 128 * 136;          // 17536
static constexpr int SMEM_FLOATS = A_OFF + 8 * 4 * 1024;  // 50304
static constexpr int SMEM_BYTES  = SMEM_FLOATS * 4;       // 201216

__device__ __forceinline__ uint32_t smem_u32(const void* p) {
    uint32_t a;
    asm("{ .reg .u64 t; cvta.to.shared.u64 t, %1; cvt.u32.u64 %0, t; }" : "=r"(a) : "l"(p));
    return a;
}
__device__ __forceinline__ void cpasync16(uint32_t dst, const float* src) {
    asm volatile("cp.async.cg.shared.global [%0], [%1], 16;" :: "r"(dst), "l"(src) : "memory");
}
__device__ __forceinline__ void cpcommit() {
    asm volatile("cp.async.commit_group;" ::: "memory");
}
template <int N> __device__ __forceinline__ void cpwait() {
    asm volatile("cp.async.wait_group %0;" :: "n"(N) : "memory");
}
__device__ __forceinline__ void barpair(int id) {
    asm volatile("bar.sync %0, 64;" :: "r"(id) : "memory");
}
__device__ __forceinline__ uint32_t pack_h2(float lo, float hi) {
    uint32_t r;
    asm("cvt.rn.f16x2.f32 %0, %1, %2;" : "=r"(r) : "f"(hi), "f"(lo));
    return r;
}
__device__ __forceinline__ void lds_v2f(uint32_t addr, float& f0, float& f1) {
    asm volatile("ld.shared.v2.f32 {%0, %1}, [%2];" : "=f"(f0), "=f"(f1) : "r"(addr));
}
__device__ __forceinline__ void lds_v2u(uint32_t addr, uint32_t& v0, uint32_t& v1) {
    asm volatile("ld.shared.v2.b32 {%0, %1}, [%2];" : "=r"(v0), "=r"(v1) : "r"(addr));
}
__device__ __forceinline__ void mma16(float* c, const uint32_t* a, uint32_t b0, uint32_t b1) {
    asm volatile(
        "mma.sync.aligned.m16n8k16.row.col.f32.f16.f16.f32 "
        "{%0,%1,%2,%3}, {%4,%5,%6,%7}, {%8,%9}, {%0,%1,%2,%3};"
        : "+f"(c[0]), "+f"(c[1]), "+f"(c[2]), "+f"(c[3])
        : "r"(a[0]), "r"(a[1]), "r"(a[2]), "r"(a[3]), "r"(b0), "r"(b1));
}
// JAX demotes int64->int32 silently; detect layout from first 32 bytes.
__device__ __forceinline__ int get_var(const int* __restrict__ p32, int v) {
    bool is64 = ((p32[1] | p32[3] | p32[5] | p32[7]) == 0);
    return is64 ? p32[2 * v] : p32[v];
}

__global__ __launch_bounds__(THREADS, 1)
void pve_mma_kernel(const float* __restrict__ x,
                    const int* __restrict__ in_vars,
                    const float* __restrict__ w,
                    const float* __restrict__ bias,
                    float* __restrict__ out)
{
    extern __shared__ float smf[];
    const uint32_t sbase = smem_u32(smf);

    const int tid  = threadIdx.x;
    const int wid  = tid >> 5;
    const int lane = tid & 31;
    const int qrow = lane >> 2;     // 0..7
    const int qcol = lane & 3;      // 0..3
    const int pair = wid >> 1;      // 0..7
    const int wpos = wid & 1;       // n-half
    const int pr   = pair & 3;      // m-quarter (patch row group)
    const int bset = pair >> 2;     // batch half within bg
    const int ptid = wpos * 32 + lane;
    const int n0   = wpos * 64;

    const int rg = blockIdx.x, v = blockIdx.y, bg = blockIdx.z;
    const int var = get_var(in_vars, v);

    const float* wbase = w + (size_t)var * (128 * 256);

    if (tid < 128) smf[BIAS_OFF + tid] = bias[var * 128 + tid];

    // ---- B prologue: W[var] -> fp16 -> resident [128 rows][136 u32] ----
    uint32_t* bres = reinterpret_cast<uint32_t*>(smf + B_OFF);
    #pragma unroll
    for (int i = 0; i < 16; i++) {
        int idx = tid + 512 * i;            // 0..8191 float4s
        int e   = idx >> 6;                 // 0..127
        int k4  = idx & 63;
        float4 vsrc = *reinterpret_cast<const float4*>(wbase + (size_t)e * 256 + k4 * 4);
        uint32_t p0 = pack_h2(vsrc.x, vsrc.y);   // pair 2*k4
        uint32_t p1 = pack_h2(vsrc.z, vsrc.w);   // pair 2*k4+1
        int pa = 2 * k4, pb = 2 * k4 + 1;
        uint32_t* row = bres + e * 136;
        row[(pa >> 3) * 8 + (pa & 3) * 2 + ((pa >> 2) & 1)] = p0;
        row[(pb >> 3) * 8 + (pb & 3) * 2 + ((pb >> 2) & 1)] = p1;
    }
    __syncthreads();   // last CTA-wide barrier; pairs run free after this

    // ---- per-thread invariant A copy mapping (rotation layout) ----
    uint32_t dst_inv[4];
    int      src_inv[4];
    #pragma unroll
    for (int i = 0; i < 4; i++) {
        int idx = ptid + 64 * i;
        int dp  = idx >> 7, c4 = idx & 127;
        int mp  = c4 >> 2;
        int kl  = dp * 16 + (c4 & 3) * 4;
        dst_inv[i] = (uint32_t)(mp * 32 + ((kl + 8 * (mp & 7)) & 31));
        src_inv[i] = dp * 512 + c4 * 4;
    }

    const uint32_t apair = (uint32_t)(A_OFF + pair * 4096);   // 4 stages x 1024 fl
    const float* xpr[4];
    #pragma unroll
    for (int bi = 0; bi < 4; bi++) {
        int b = bg * 8 + bset * 4 + bi;
        xpr[bi] = x + (size_t)(b * 8 + v) * (512 * 512)
                    + (size_t)(rg * 64 + pr * 16) * 512;
    }

    auto issueA = [&](int t) {
        const float* src = xpr[t >> 3] + (t & 7) * 1024;
        const uint32_t abase = sbase + (apair + (uint32_t)((t & 3) * 1024)) * 4;
        #pragma unroll
        for (int i = 0; i < 4; i++)
            cpasync16(abase + dst_inv[i] * 4, src + src_inv[i]);
        cpcommit();
    };

    // loop-invariant fragment offsets
    uint32_t akoff[2][2];
    #pragma unroll
    for (int s = 0; s < 2; s++) {
        akoff[s][0] = (uint32_t)(((s * 16 + qcol * 2     + 8 * qrow) & 31) * 4);
        akoff[s][1] = (uint32_t)(((s * 16 + qcol * 2 + 8 + 8 * qrow) & 31) * 4);
    }
    const uint32_t arow0 = (uint32_t)qrow * 128;
    const uint32_t bfrag0 = (uint32_t)(B_OFF + (n0 + qrow) * 136 + qcol * 2) * 4;

    float acc[2][8][4];
    #pragma unroll
    for (int mf = 0; mf < 2; mf++)
        #pragma unroll
        for (int nf = 0; nf < 8; nf++)
            #pragma unroll
            for (int j = 0; j < 4; j++) acc[mf][nf][j] = 0.0f;

    issueA(0); issueA(1); issueA(2);

    #pragma unroll 1
    for (int t = 0; t < 32; t++) {
        if (t < 30)       cpwait<2>();
        else if (t == 30) cpwait<1>();
        else              cpwait<0>();
        barpair(pair + 1);           // chunk t visible; slot (t+3)&3 fully consumed
        if (t + 3 < 32) issueA(t + 3);

        const uint32_t aR0 = sbase + (apair + (uint32_t)((t & 3) * 1024)) * 4 + arow0;
        const uint32_t bR0 = sbase + bfrag0 + (uint32_t)((t & 7) * 2) * 32;

        #pragma unroll
        for (int s = 0; s < 2; s++) {           // two k16 steps per chunk
            const uint32_t k0 = akoff[s][0], k1 = akoff[s][1];
            uint32_t a[2][4];
            #pragma unroll
            for (int mf = 0; mf < 2; mf++) {
                const uint32_t r0 = aR0 + (uint32_t)(mf * 16) * 128;
                float f0, f1;
                lds_v2f(r0 + k0,           f0, f1); a[mf][0] = pack_h2(f0, f1);
                lds_v2f(r0 + 8 * 128 + k0, f0, f1); a[mf][1] = pack_h2(f0, f1);
                lds_v2f(r0 + k1,           f0, f1); a[mf][2] = pack_h2(f0, f1);
                lds_v2f(r0 + 8 * 128 + k1, f0, f1); a[mf][3] = pack_h2(f0, f1);
            }
            const uint32_t bks = bR0 + (uint32_t)(s * 8) * 4;
            #pragma unroll
            for (int nf = 0; nf < 8; nf++) {
                uint32_t b0, b1;
                lds_v2u(bks + (uint32_t)(nf * 8) * (136 * 4), b0, b1);
                mma16(acc[0][nf], a[0], b0, b1);
                mma16(acc[1][nf], a[1], b0, b1);
            }
        }

        if ((t & 7) == 7) {
            const int b = bg * 8 + bset * 4 + (t >> 3);
            float* obase = out + (((size_t)(b * 8 + v) * 1024) + (size_t)rg * 128) * 128;
            const float* bs = smf + BIAS_OFF;
            #pragma unroll
            for (int mf = 0; mf < 2; mf++) {
                const int r = pr * 32 + mf * 16 + qrow;
                #pragma unroll
                for (int nf = 0; nf < 8; nf++) {
                    const int e0 = n0 + nf * 8 + qcol * 2;
                    float2 lo, hi;
                    lo.x = acc[mf][nf][0] + bs[e0];
                    lo.y = acc[mf][nf][1] + bs[e0 + 1];
                    hi.x = acc[mf][nf][2] + bs[e0];
                    hi.y = acc[mf][nf][3] + bs[e0 + 1];
                    *reinterpret_cast<float2*>(obase + (size_t)r * 128 + e0)       = lo;
                    *reinterpret_cast<float2*>(obase + (size_t)(r + 8) * 128 + e0) = hi;
                    acc[mf][nf][0] = 0.0f; acc[mf][nf][1] = 0.0f;
                    acc[mf][nf][2] = 0.0f; acc[mf][nf][3] = 0.0f;
                }
            }
        }
    }
}

extern "C" void kernel_launch(void* const* d_in, const int* in_sizes, int n_in,
                              void* d_out, int out_size)
{
    const float* x       = (const float*)d_in[0];
    const int*   in_vars = (const int*)d_in[1];
    const float* w       = (const float*)d_in[2];
    const float* bias    = (const float*)d_in[3];
    float*       out     = (float*)d_out;

    cudaFuncSetAttribute(pve_mma_kernel,
                         cudaFuncAttributeMaxDynamicSharedMemorySize, SMEM_BYTES);

    dim3 grid(8, 8, 2);    // (row group, V, batch group) -> 128 persistent CTAs
    pve_mma_kernel<<<grid, THREADS, SMEM_BYTES>>>(x, in_vars, w, bias, out);
}